// round 1
// baseline (speedup 1.0000x reference)
#include <cuda_runtime.h>

#define NX 192
#define NY 192
#define NZ 192
#define NB 2
#define WIN 9
#define PAD 4
#define WS_INV (1.0f / 729.0f)
#define EPS 1e-5f

constexpr size_t NTOT = (size_t)NB * NX * NY * NZ;   // 14,155,776
constexpr size_t STRX = (size_t)NY * NZ;             // stride along X

// Scratch: 5 channels {I_sum, J_sum, I2_sum, J2_sum, IJ_sum}, ping-pong buffers.
__device__ float  g_bufA[5 * NTOT];
__device__ float  g_bufB[5 * NTOT];
__device__ double g_accum;

__global__ void zero_accum_kernel() { g_accum = 0.0; }

// ---------------------------------------------------------------------------
// Pass 1: 9-tap box sum along Z (contiguous). One block = one (b,x,y) line.
// Reads I, J once; writes the 5 quantity channels, Z-filtered.
// ---------------------------------------------------------------------------
__global__ void pass1_z(const float* __restrict__ I, const float* __restrict__ J) {
    __shared__ float sI[NZ + 2 * PAD];
    __shared__ float sJ[NZ + 2 * PAD];
    const int line = blockIdx.x;          // 0 .. NB*NX*NY-1
    const int z = threadIdx.x;            // 0 .. 191
    const size_t base = (size_t)line * NZ;

    const float a = I[base + z];
    const float b = J[base + z];
    sI[z + PAD] = a;
    sJ[z + PAD] = b;
    if (z < PAD) {
        sI[z] = 0.f;            sJ[z] = 0.f;
        sI[NZ + PAD + z] = 0.f; sJ[NZ + PAD + z] = 0.f;
    }
    __syncthreads();

    float s1 = 0.f, s2 = 0.f, s3 = 0.f, s4 = 0.f, s5 = 0.f;
#pragma unroll
    for (int k = 0; k < WIN; k++) {
        const float u = sI[z + k];
        const float v = sJ[z + k];
        s1 += u;       s2 += v;
        s3 += u * u;   s4 += v * v;
        s5 += u * v;
    }
    const size_t idx = base + z;
    g_bufA[0 * NTOT + idx] = s1;
    g_bufA[1 * NTOT + idx] = s2;
    g_bufA[2 * NTOT + idx] = s3;
    g_bufA[3 * NTOT + idx] = s4;
    g_bufA[4 * NTOT + idx] = s5;
}

// ---------------------------------------------------------------------------
// Pass 2: sliding-window box sum along Y for each channel.
// Block = (channel, b, x) plane; thread = z (coalesced). Subtract stream
// re-reads an address this thread touched 8 iterations ago -> L1/L2 hit.
// ---------------------------------------------------------------------------
__global__ void pass2_y() {
    const int id = blockIdx.x;                 // 0 .. 5*NB*NX-1
    const int q  = id / (NB * NX);
    const int bx = id % (NB * NX);
    const int z  = threadIdx.x;

    const float* __restrict__ in  = g_bufA + (size_t)q * NTOT + (size_t)bx * NY * NZ + z;
    float*       __restrict__ out = g_bufB + (size_t)q * NTOT + (size_t)bx * NY * NZ + z;

    float s = 0.f;
#pragma unroll
    for (int y = 0; y < PAD; y++) s += in[(size_t)y * NZ];

    for (int y = 0; y < NY; y++) {
        const int yp = y + PAD;
        if (yp < NY) s += in[(size_t)yp * NZ];
        out[(size_t)y * NZ] = s;
        const int ym = y - PAD;
        if (ym >= 0) s -= in[(size_t)ym * NZ];
    }
}

// ---------------------------------------------------------------------------
// Pass 3: sliding-window box sum along X on all 5 channels at once, fused
// NCC computation and global mean reduction.
// Thread = (b, y, z) line; consecutive threads -> consecutive z (coalesced).
// ---------------------------------------------------------------------------
__global__ void pass3_x_ncc() {
    const int t  = blockIdx.x * blockDim.x + threadIdx.x;  // 0 .. NB*NY*NZ-1
    const int b  = t / (NY * NZ);
    const int yz = t % (NY * NZ);
    const float* __restrict__ p = g_bufB + (size_t)b * NX * NY * NZ + yz;

    float s0 = 0.f, s1 = 0.f, s2 = 0.f, s3 = 0.f, s4 = 0.f;
#pragma unroll
    for (int x = 0; x < PAD; x++) {
        const size_t o = (size_t)x * STRX;
        s0 += p[0 * NTOT + o]; s1 += p[1 * NTOT + o]; s2 += p[2 * NTOT + o];
        s3 += p[3 * NTOT + o]; s4 += p[4 * NTOT + o];
    }

    float acc = 0.f;
    for (int x = 0; x < NX; x++) {
        const int xp = x + PAD;
        if (xp < NX) {
            const size_t o = (size_t)xp * STRX;
            s0 += p[0 * NTOT + o]; s1 += p[1 * NTOT + o]; s2 += p[2 * NTOT + o];
            s3 += p[3 * NTOT + o]; s4 += p[4 * NTOT + o];
        }
        const float cross = s4 - s0 * s1 * WS_INV;
        const float ivar  = s2 - s0 * s0 * WS_INV;
        const float jvar  = s3 - s1 * s1 * WS_INV;
        acc += (cross * cross) / (ivar * jvar + EPS);
        const int xm = x - PAD;
        if (xm >= 0) {
            const size_t o = (size_t)xm * STRX;
            s0 -= p[0 * NTOT + o]; s1 -= p[1 * NTOT + o]; s2 -= p[2 * NTOT + o];
            s3 -= p[3 * NTOT + o]; s4 -= p[4 * NTOT + o];
        }
    }

    __shared__ float red[256];
    red[threadIdx.x] = acc;
    __syncthreads();
#pragma unroll
    for (int o = 128; o > 0; o >>= 1) {
        if (threadIdx.x < o) red[threadIdx.x] += red[threadIdx.x + o];
        __syncthreads();
    }
    if (threadIdx.x == 0) atomicAdd(&g_accum, (double)red[0]);
}

__global__ void finalize_kernel(float* __restrict__ out) {
    out[0] = (float)(-g_accum / (double)NTOT);
}

extern "C" void kernel_launch(void* const* d_in, const int* in_sizes, int n_in,
                              void* d_out, int out_size) {
    const float* I = (const float*)d_in[0];
    const float* J = (const float*)d_in[1];
    float* out = (float*)d_out;

    zero_accum_kernel<<<1, 1>>>();
    pass1_z<<<NB * NX * NY, NZ>>>(I, J);
    pass2_y<<<5 * NB * NX, NZ>>>();
    pass3_x_ncc<<<(NB * NY * NZ) / 256, 256>>>();
    finalize_kernel<<<1, 1>>>(out);
}

// round 2
// speedup vs baseline: 2.1258x; 2.1258x over previous
#include <cuda_runtime.h>

#define NX 192
#define NY 192
#define NZ 192
#define NB 2
#define WIN 9
#define PAD 4
#define WS_INV (1.0f / 729.0f)
#define EPS 1e-5f

#define YCHUNKS 2
#define YC (NY / YCHUNKS)      /* 96 */
#define XCHUNKS 4
#define XC (NX / XCHUNKS)      /* 48 */

constexpr size_t NTOT = (size_t)NB * NX * NY * NZ;   // 14,155,776
constexpr size_t STRX = (size_t)NY * NZ;             // stride along X

// Scratch: 5 channels {I_sum, J_sum, I2_sum, J2_sum, IJ_sum}, Z+Y filtered.
__device__ float  g_buf[5 * NTOT];
__device__ double g_accum;

__global__ void zero_accum_kernel() { g_accum = 0.0; }

__device__ __forceinline__ int ring_slot(int r) { return ((r % 9) + 9) % 9; }

// ---------------------------------------------------------------------------
// pass12: fused Z-filter (9-tap over contiguous z, via smem row with halo)
// + Y-filter (sliding 9-row window: smem ring buffer + register running sums).
// Block = (b, x, y-chunk); thread = z. Reads I,J once, writes 5 channels once.
// ---------------------------------------------------------------------------
__global__ __launch_bounds__(NZ) void pass12(const float* __restrict__ I,
                                             const float* __restrict__ J) {
    __shared__ float sI[NZ + 2 * PAD];
    __shared__ float sJ[NZ + 2 * PAD];
    __shared__ float ring[9][5][NZ];          // 34.56 KB

    const int id = blockIdx.x;                // 0 .. NB*NX*YCHUNKS-1
    const int yc = id % YCHUNKS;
    const int bx = id / YCHUNKS;              // (b,x)
    const int z  = threadIdx.x;

    const size_t planeBase = (size_t)bx * NY * NZ;  // elem offset of (b,x,0,0)
    const int y0 = yc * YC;
    const int y1 = y0 + YC;

    if (z < PAD) {
        sI[z] = 0.f;            sJ[z] = 0.f;
        sI[NZ + PAD + z] = 0.f; sJ[NZ + PAD + z] = 0.f;
    }

    float s0 = 0.f, s1 = 0.f, s2 = 0.f, s3 = 0.f, s4 = 0.f;

    for (int yl = y0 - PAD; yl < y1 + PAD; ++yl) {
        const bool inr = (yl >= 0) && (yl < NY);
        __syncthreads();                       // protect prior taps before overwrite
        if (inr) {
            const size_t off = planeBase + (size_t)yl * NZ + z;
            sI[PAD + z] = I[off];
            sJ[PAD + z] = J[off];
        }
        __syncthreads();

        float q0 = 0.f, q1 = 0.f, q2 = 0.f, q3 = 0.f, q4 = 0.f;
        if (inr) {
#pragma unroll
            for (int k = 0; k < WIN; k++) {
                const float u = sI[z + k];
                const float v = sJ[z + k];
                q0 += u;      q1 += v;
                q2 += u * u;  q3 += v * v;
                q4 += u * v;
            }
        }
        const int sl = ring_slot(yl);
        ring[sl][0][z] = q0;  ring[sl][1][z] = q1;  ring[sl][2][z] = q2;
        ring[sl][3][z] = q3;  ring[sl][4][z] = q4;
        s0 += q0; s1 += q1; s2 += q2; s3 += q3; s4 += q4;

        if (yl >= y0 + PAD) {
            const int yo = yl - PAD;
            const size_t o = planeBase + (size_t)yo * NZ + z;
            g_buf[0 * NTOT + o] = s0;
            g_buf[1 * NTOT + o] = s1;
            g_buf[2 * NTOT + o] = s2;
            g_buf[3 * NTOT + o] = s3;
            g_buf[4 * NTOT + o] = s4;
            const int sm = ring_slot(yl - 2 * PAD);
            s0 -= ring[sm][0][z]; s1 -= ring[sm][1][z]; s2 -= ring[sm][2][z];
            s3 -= ring[sm][3][z]; s4 -= ring[sm][4][z];
        }
    }
}

// ---------------------------------------------------------------------------
// pass3: sliding 9-slice window along X on all 5 channels, fused NCC + mean.
// X is split into XCHUNKS ranges per (b,y,z) line for 4x more parallelism.
// Thread = (b, y, z) line; consecutive threads -> consecutive z (coalesced).
// ---------------------------------------------------------------------------
__global__ __launch_bounds__(256) void pass3_x_ncc() {
    const int x0 = blockIdx.y * XC;
    const int t  = blockIdx.x * blockDim.x + threadIdx.x;  // 0 .. NB*NY*NZ-1
    const int b  = t / (NY * NZ);
    const int yz = t % (NY * NZ);
    const float* __restrict__ p = g_buf + (size_t)b * NX * NY * NZ + yz;

    float s0 = 0.f, s1 = 0.f, s2 = 0.f, s3 = 0.f, s4 = 0.f;
    const int pre0 = (x0 - PAD > 0) ? (x0 - PAD) : 0;
#pragma unroll 4
    for (int x = pre0; x < x0 + PAD; ++x) {     // x0+PAD <= 148 < NX always
        const size_t o = (size_t)x * STRX;
        s0 += p[0 * NTOT + o]; s1 += p[1 * NTOT + o]; s2 += p[2 * NTOT + o];
        s3 += p[3 * NTOT + o]; s4 += p[4 * NTOT + o];
    }

    float acc = 0.f;
#pragma unroll 2
    for (int x = x0; x < x0 + XC; ++x) {
        const int xp = x + PAD;
        if (xp < NX) {
            const size_t o = (size_t)xp * STRX;
            s0 += p[0 * NTOT + o]; s1 += p[1 * NTOT + o]; s2 += p[2 * NTOT + o];
            s3 += p[3 * NTOT + o]; s4 += p[4 * NTOT + o];
        }
        const float cross = s4 - s0 * s1 * WS_INV;
        const float ivar  = s2 - s0 * s0 * WS_INV;
        const float jvar  = s3 - s1 * s1 * WS_INV;
        acc += (cross * cross) / (ivar * jvar + EPS);
        const int xm = x - PAD;
        if (xm >= 0) {
            const size_t o = (size_t)xm * STRX;
            s0 -= p[0 * NTOT + o]; s1 -= p[1 * NTOT + o]; s2 -= p[2 * NTOT + o];
            s3 -= p[3 * NTOT + o]; s4 -= p[4 * NTOT + o];
        }
    }

    __shared__ float red[256];
    red[threadIdx.x] = acc;
    __syncthreads();
#pragma unroll
    for (int o = 128; o > 0; o >>= 1) {
        if (threadIdx.x < o) red[threadIdx.x] += red[threadIdx.x + o];
        __syncthreads();
    }
    if (threadIdx.x == 0) atomicAdd(&g_accum, (double)red[0]);
}

__global__ void finalize_kernel(float* __restrict__ out) {
    out[0] = (float)(-g_accum / (double)NTOT);
}

extern "C" void kernel_launch(void* const* d_in, const int* in_sizes, int n_in,
                              void* d_out, int out_size) {
    const float* I = (const float*)d_in[0];
    const float* J = (const float*)d_in[1];
    float* out = (float*)d_out;

    zero_accum_kernel<<<1, 1>>>();
    pass12<<<NB * NX * YCHUNKS, NZ>>>(I, J);
    {
        dim3 grid((NB * NY * NZ) / 256, XCHUNKS);
        pass3_x_ncc<<<grid, 256>>>();
    }
    finalize_kernel<<<1, 1>>>(out);
}

// round 3
// speedup vs baseline: 2.7427x; 1.2902x over previous
#include <cuda_runtime.h>
#include <cuda_fp16.h>

#define NX 192
#define NY 192
#define NZ 192
#define NB 2
#define WIN 9
#define PAD 4
#define WS_INV (1.0f / 729.0f)
#define EPS 1e-5f

#define YCHUNKS 2
#define YC (NY / YCHUNKS)      /* 96 */
#define XCHUNKS 4
#define XC (NX / XCHUNKS)      /* 48 */

constexpr size_t NTOT = (size_t)NB * NX * NY * NZ;   // 14,155,776
constexpr int HALF_PLANE = NY * NZ / 2;              // half2 elems per x-slice
constexpr int STRX2 = HALF_PLANE;                    // x stride in half2 units
constexpr size_t NTOT2 = NTOT / 2;                   // half2 elems per channel

// Scratch: 5 channels {I_sum, J_sum, I2_sum, J2_sum, IJ_sum}, Z+Y filtered, fp16.
__device__ __half  g_buf[5 * NTOT];
__device__ double  g_accum;

__global__ void zero_accum_kernel() { g_accum = 0.0; }

__device__ __forceinline__ int ring_slot(int r) { return ((r % 9) + 9) % 9; }

// ---------------------------------------------------------------------------
// pass12: fused Z-filter (9-tap via smem row + halo) + Y-filter (sliding
// 9-row window: smem ring + register running sums). Global row loads are
// software-pipelined one y-iteration ahead to hide DRAM latency behind the
// tap compute. Writes fp16.
// ---------------------------------------------------------------------------
__global__ __launch_bounds__(NZ) void pass12(const float* __restrict__ I,
                                             const float* __restrict__ J) {
    __shared__ float sI[NZ + 2 * PAD];
    __shared__ float sJ[NZ + 2 * PAD];
    __shared__ float ring[9][5][NZ];          // 34.56 KB

    const int id = blockIdx.x;                // 0 .. NB*NX*YCHUNKS-1
    const int yc = id % YCHUNKS;
    const int bx = id / YCHUNKS;              // (b,x)
    const int z  = threadIdx.x;

    const size_t planeBase = (size_t)bx * NY * NZ;
    const int y0 = yc * YC;
    const int y1 = y0 + YC;
    const int ylEnd = y1 + PAD;

    if (z < PAD) {
        sI[z] = 0.f;            sJ[z] = 0.f;
        sI[NZ + PAD + z] = 0.f; sJ[NZ + PAD + z] = 0.f;
    }

    // Prefetch first row into registers.
    int yl0 = y0 - PAD;
    float aI = 0.f, aJ = 0.f;
    if (yl0 >= 0) {
        const size_t off = planeBase + (size_t)yl0 * NZ + z;
        aI = I[off];
        aJ = J[off];
    }

    float s0 = 0.f, s1 = 0.f, s2 = 0.f, s3 = 0.f, s4 = 0.f;

    for (int yl = yl0; yl < ylEnd; ++yl) {
        __syncthreads();                       // prior taps consumed
        sI[PAD + z] = aI;
        sJ[PAD + z] = aJ;
        __syncthreads();

        // Prefetch next row (overlaps with tap compute below).
        const int yn = yl + 1;
        if (yn >= 0 && yn < NY && yn < ylEnd) {
            const size_t off = planeBase + (size_t)yn * NZ + z;
            aI = I[off];
            aJ = J[off];
        } else {
            aI = 0.f;
            aJ = 0.f;
        }

        float q0 = 0.f, q1 = 0.f, q2 = 0.f, q3 = 0.f, q4 = 0.f;
#pragma unroll
        for (int k = 0; k < WIN; k++) {
            const float u = sI[z + k];
            const float v = sJ[z + k];
            q0 += u;      q1 += v;
            q2 += u * u;  q3 += v * v;
            q4 += u * v;
        }
        const int sl = ring_slot(yl);
        ring[sl][0][z] = q0;  ring[sl][1][z] = q1;  ring[sl][2][z] = q2;
        ring[sl][3][z] = q3;  ring[sl][4][z] = q4;
        s0 += q0; s1 += q1; s2 += q2; s3 += q3; s4 += q4;

        if (yl >= y0 + PAD) {
            const int yo = yl - PAD;
            const size_t o = planeBase + (size_t)yo * NZ + z;
            g_buf[0 * NTOT + o] = __float2half_rn(s0);
            g_buf[1 * NTOT + o] = __float2half_rn(s1);
            g_buf[2 * NTOT + o] = __float2half_rn(s2);
            g_buf[3 * NTOT + o] = __float2half_rn(s3);
            g_buf[4 * NTOT + o] = __float2half_rn(s4);
            const int sm = ring_slot(yl - 2 * PAD);
            s0 -= ring[sm][0][z]; s1 -= ring[sm][1][z]; s2 -= ring[sm][2][z];
            s3 -= ring[sm][3][z]; s4 -= ring[sm][4][z];
        }
    }
}

// ---------------------------------------------------------------------------
// pass3: sliding 9-slice window along X, fused NCC + mean. fp16 scratch read
// as half2 (2 z-voxels per thread -> 128B warp lines per channel, 2x MLP).
// X split into XCHUNKS ranges for parallelism.
// ---------------------------------------------------------------------------
__global__ __launch_bounds__(256) void pass3_x_ncc() {
    const int x0 = blockIdx.y * XC;
    const int t  = blockIdx.x * blockDim.x + threadIdx.x;  // 0 .. NB*NY*NZ/2-1
    const int b  = t / HALF_PLANE;
    const int yz = t % HALF_PLANE;

    const __half2* __restrict__ p0 =
        reinterpret_cast<const __half2*>(g_buf + 0 * NTOT) + (size_t)b * NX * HALF_PLANE + yz;
    const __half2* __restrict__ p1 = p0 + 1 * NTOT2;
    const __half2* __restrict__ p2 = p0 + 2 * NTOT2;
    const __half2* __restrict__ p3 = p0 + 3 * NTOT2;
    const __half2* __restrict__ p4 = p0 + 4 * NTOT2;

    float a0 = 0.f, a1 = 0.f, a2 = 0.f, a3 = 0.f, a4 = 0.f;  // lane .x sums
    float b0 = 0.f, b1 = 0.f, b2 = 0.f, b3 = 0.f, b4 = 0.f;  // lane .y sums

    const int pre0 = (x0 - PAD > 0) ? (x0 - PAD) : 0;
#pragma unroll 4
    for (int x = pre0; x < x0 + PAD; ++x) {
        const size_t o = (size_t)x * STRX2;
        float2 f0 = __half22float2(p0[o]); a0 += f0.x; b0 += f0.y;
        float2 f1 = __half22float2(p1[o]); a1 += f1.x; b1 += f1.y;
        float2 f2 = __half22float2(p2[o]); a2 += f2.x; b2 += f2.y;
        float2 f3 = __half22float2(p3[o]); a3 += f3.x; b3 += f3.y;
        float2 f4 = __half22float2(p4[o]); a4 += f4.x; b4 += f4.y;
    }

    float acc = 0.f;
#pragma unroll 2
    for (int x = x0; x < x0 + XC; ++x) {
        const int xp = x + PAD;
        if (xp < NX) {
            const size_t o = (size_t)xp * STRX2;
            float2 f0 = __half22float2(p0[o]); a0 += f0.x; b0 += f0.y;
            float2 f1 = __half22float2(p1[o]); a1 += f1.x; b1 += f1.y;
            float2 f2 = __half22float2(p2[o]); a2 += f2.x; b2 += f2.y;
            float2 f3 = __half22float2(p3[o]); a3 += f3.x; b3 += f3.y;
            float2 f4 = __half22float2(p4[o]); a4 += f4.x; b4 += f4.y;
        }
        {
            const float cross = a4 - a0 * a1 * WS_INV;
            const float ivar  = a2 - a0 * a0 * WS_INV;
            const float jvar  = a3 - a1 * a1 * WS_INV;
            acc += (cross * cross) / (ivar * jvar + EPS);
        }
        {
            const float cross = b4 - b0 * b1 * WS_INV;
            const float ivar  = b2 - b0 * b0 * WS_INV;
            const float jvar  = b3 - b1 * b1 * WS_INV;
            acc += (cross * cross) / (ivar * jvar + EPS);
        }
        const int xm = x - PAD;
        if (xm >= 0) {
            const size_t o = (size_t)xm * STRX2;
            float2 f0 = __half22float2(p0[o]); a0 -= f0.x; b0 -= f0.y;
            float2 f1 = __half22float2(p1[o]); a1 -= f1.x; b1 -= f1.y;
            float2 f2 = __half22float2(p2[o]); a2 -= f2.x; b2 -= f2.y;
            float2 f3 = __half22float2(p3[o]); a3 -= f3.x; b3 -= f3.y;
            float2 f4 = __half22float2(p4[o]); a4 -= f4.x; b4 -= f4.y;
        }
    }

    __shared__ float red[256];
    red[threadIdx.x] = acc;
    __syncthreads();
#pragma unroll
    for (int o = 128; o > 0; o >>= 1) {
        if (threadIdx.x < o) red[threadIdx.x] += red[threadIdx.x + o];
        __syncthreads();
    }
    if (threadIdx.x == 0) atomicAdd(&g_accum, (double)red[0]);
}

__global__ void finalize_kernel(float* __restrict__ out) {
    out[0] = (float)(-g_accum / (double)NTOT);
}

extern "C" void kernel_launch(void* const* d_in, const int* in_sizes, int n_in,
                              void* d_out, int out_size) {
    const float* I = (const float*)d_in[0];
    const float* J = (const float*)d_in[1];
    float* out = (float*)d_out;

    zero_accum_kernel<<<1, 1>>>();
    pass12<<<NB * NX * YCHUNKS, NZ>>>(I, J);
    {
        dim3 grid((NB * NY * NZ / 2) / 256, XCHUNKS);
        pass3_x_ncc<<<grid, 256>>>();
    }
    finalize_kernel<<<1, 1>>>(out);
}

// round 6
// speedup vs baseline: 3.1181x; 1.1369x over previous
#include <cuda_runtime.h>
#include <cuda_fp16.h>

#define NX 192
#define NY 192
#define NZ 192
#define NB 2
#define WIN 9
#define PAD 4
#define WS_INV (1.0f / 729.0f)
#define EPS 1e-5f

#define YC 96                   /* y-chunk per threadIdx.y */
#define XCHUNKS 4
#define XC (NX / XCHUNKS)       /* 48 */
#define NZ2 (NZ / 2)            /* 96 float2/half2 per row */

constexpr size_t NTOT  = (size_t)NB * NX * NY * NZ;   // 14,155,776
constexpr size_t NTOT2 = NTOT / 2;                    // half2 elems per channel
constexpr int HALF_PLANE = NY * NZ / 2;               // half2 per x-slice

// Scratch: 5 channels {I_sum, J_sum, I2_sum, J2_sum, IJ_sum}, Z+Y filtered, fp16.
__device__ __half  g_buf[5 * NTOT];
__device__ double  g_accum;

// Persistent-state management: dedicated kernels (R1-R3 proven; fused variants failed).
__global__ void zero_accum_kernel() { g_accum = 0.0; }
__global__ void finalize_kernel(float* __restrict__ out) {
    out[0] = (float)(-g_accum / (double)NTOT);
}

// ---------------------------------------------------------------------------
// pass12: fused Z-filter + Y-filter. Thread = float2 z-pair; threadIdx.y = y
// chunk. Taps use shared-middle decomposition (10-wide window -> 2 outputs).
// Ring buffer holds per-row quantity pairs in half2. Software-pipelined
// global row loads. Two barriers per row (R4 structure, unchanged).
// ---------------------------------------------------------------------------
__global__ __launch_bounds__(192) void pass12(const float* __restrict__ I,
                                              const float* __restrict__ J) {
    __shared__ float2  sIf[2][NZ2 + PAD];          // 100 float2 per chunk
    __shared__ float2  sJf[2][NZ2 + PAD];
    __shared__ __half2 ring[2][9][5][NZ2];         // 34.56 KB

    const int c  = threadIdx.y;                    // y-chunk 0/1
    const int tz = threadIdx.x;                    // 0..95
    const int bx = blockIdx.x;                     // (b,x): 0..NB*NX-1
    const size_t planeBase = (size_t)bx * NY * NZ;
    const int y0 = c * YC;
    const int ylEnd = y0 + YC + PAD;

    if (tz < 2) {   // z halo: floats [0..3] and [196..199] as 2 float2 each side
        sIf[c][tz] = make_float2(0.f, 0.f);
        sJf[c][tz] = make_float2(0.f, 0.f);
        sIf[c][NZ2 + 2 + tz] = make_float2(0.f, 0.f);
        sJf[c][NZ2 + 2 + tz] = make_float2(0.f, 0.f);
    }

    const float2* __restrict__ I2 = reinterpret_cast<const float2*>(I + planeBase);
    const float2* __restrict__ J2 = reinterpret_cast<const float2*>(J + planeBase);
    __half2* __restrict__ h2buf = reinterpret_cast<__half2*>(g_buf);

    const int yl0 = y0 - PAD;
    float2 aI = make_float2(0.f, 0.f), aJ = make_float2(0.f, 0.f);
    if (yl0 >= 0) {
        aI = I2[(size_t)yl0 * NZ2 + tz];
        aJ = J2[(size_t)yl0 * NZ2 + tz];
    }

    float sA0 = 0.f, sA1 = 0.f, sA2 = 0.f, sA3 = 0.f, sA4 = 0.f;
    float sB0 = 0.f, sB1 = 0.f, sB2 = 0.f, sB3 = 0.f, sB4 = 0.f;
    int slot = ((yl0 % 9) + 9) % 9;

    for (int yl = yl0; yl < ylEnd; ++yl) {
        __syncthreads();                   // prior row's taps consumed
        sIf[c][tz + 2] = aI;
        sJf[c][tz + 2] = aJ;
        __syncthreads();

        // Prefetch next row (overlaps tap compute).
        const int yn = yl + 1;
        if (yn >= 0 && yn < NY && yn < ylEnd) {
            aI = I2[(size_t)yn * NZ2 + tz];
            aJ = J2[(size_t)yn * NZ2 + tz];
        } else {
            aI = make_float2(0.f, 0.f);
            aJ = make_float2(0.f, 0.f);
        }

        // Window u[0..9] = raw z (2*tz-4 .. 2*tz+5), aligned float2 reads.
        float u[10], v[10];
#pragma unroll
        for (int j = 0; j < 5; ++j) {
            const float2 tu = sIf[c][tz + j];
            const float2 tv = sJf[c][tz + j];
            u[2 * j] = tu.x; u[2 * j + 1] = tu.y;
            v[2 * j] = tv.x; v[2 * j + 1] = tv.y;
        }
        // Shared middle (taps 1..8), then edge taps for the two outputs.
        float m0 = 0.f, m1 = 0.f, m2 = 0.f, m3 = 0.f, m4 = 0.f;
#pragma unroll
        for (int i = 1; i < 9; ++i) {
            m0 += u[i];             m1 += v[i];
            m2 = fmaf(u[i], u[i], m2);
            m3 = fmaf(v[i], v[i], m3);
            m4 = fmaf(u[i], v[i], m4);
        }
        const float qA0 = m0 + u[0],                 qB0 = m0 + u[9];
        const float qA1 = m1 + v[0],                 qB1 = m1 + v[9];
        const float qA2 = fmaf(u[0], u[0], m2),      qB2 = fmaf(u[9], u[9], m2);
        const float qA3 = fmaf(v[0], v[0], m3),      qB3 = fmaf(v[9], v[9], m3);
        const float qA4 = fmaf(u[0], v[0], m4),      qB4 = fmaf(u[9], v[9], m4);

        sA0 += qA0; sA1 += qA1; sA2 += qA2; sA3 += qA3; sA4 += qA4;
        sB0 += qB0; sB1 += qB1; sB2 += qB2; sB3 += qB3; sB4 += qB4;

        ring[c][slot][0][tz] = __floats2half2_rn(qA0, qB0);
        ring[c][slot][1][tz] = __floats2half2_rn(qA1, qB1);
        ring[c][slot][2][tz] = __floats2half2_rn(qA2, qB2);
        ring[c][slot][3][tz] = __floats2half2_rn(qA3, qB3);
        ring[c][slot][4][tz] = __floats2half2_rn(qA4, qB4);

        if (yl >= y0 + PAD) {
            const int yo = yl - PAD;
            const size_t o = planeBase / 2 + (size_t)yo * NZ2 + tz;
            h2buf[0 * NTOT2 + o] = __floats2half2_rn(sA0, sB0);
            h2buf[1 * NTOT2 + o] = __floats2half2_rn(sA1, sB1);
            h2buf[2 * NTOT2 + o] = __floats2half2_rn(sA2, sB2);
            h2buf[3 * NTOT2 + o] = __floats2half2_rn(sA3, sB3);
            h2buf[4 * NTOT2 + o] = __floats2half2_rn(sA4, sB4);
            // Row yl-8 lives in slot (slot+1)%9 (read before next overwrite).
            const int so = (slot + 1 == 9) ? 0 : slot + 1;
            float2 f;
            f = __half22float2(ring[c][so][0][tz]); sA0 -= f.x; sB0 -= f.y;
            f = __half22float2(ring[c][so][1][tz]); sA1 -= f.x; sB1 -= f.y;
            f = __half22float2(ring[c][so][2][tz]); sA2 -= f.x; sB2 -= f.y;
            f = __half22float2(ring[c][so][3][tz]); sA3 -= f.x; sB3 -= f.y;
            f = __half22float2(ring[c][so][4][tz]); sA4 -= f.x; sB4 -= f.y;
        }
        slot = (slot + 1 == 9) ? 0 : slot + 1;
    }
}

// ---------------------------------------------------------------------------
// pass3 (R3-proven, verbatim structure): sliding 9-slice window along X
// (half2 per thread), fused NCC + mean via double atomicAdd. Conditional
// add/sub inside the x loop; smem tree reduction.
// ---------------------------------------------------------------------------
__global__ __launch_bounds__(256) void pass3_x_ncc() {
    const int x0 = blockIdx.y * XC;
    const int t  = blockIdx.x * blockDim.x + threadIdx.x;  // 0 .. NB*HALF_PLANE-1
    const int b  = t / HALF_PLANE;
    const int yz = t % HALF_PLANE;

    const __half2* __restrict__ p0 =
        reinterpret_cast<const __half2*>(g_buf) + (size_t)b * NX * HALF_PLANE + yz;
    const __half2* __restrict__ p1 = p0 + 1 * NTOT2;
    const __half2* __restrict__ p2 = p0 + 2 * NTOT2;
    const __half2* __restrict__ p3 = p0 + 3 * NTOT2;
    const __half2* __restrict__ p4 = p0 + 4 * NTOT2;

    float a0 = 0.f, a1 = 0.f, a2 = 0.f, a3 = 0.f, a4 = 0.f;  // lane .x sums
    float b0 = 0.f, b1 = 0.f, b2 = 0.f, b3 = 0.f, b4 = 0.f;  // lane .y sums

    const int pre0 = (x0 - PAD > 0) ? (x0 - PAD) : 0;
#pragma unroll 4
    for (int x = pre0; x < x0 + PAD; ++x) {
        const size_t o = (size_t)x * HALF_PLANE;
        float2 f0 = __half22float2(p0[o]); a0 += f0.x; b0 += f0.y;
        float2 f1 = __half22float2(p1[o]); a1 += f1.x; b1 += f1.y;
        float2 f2 = __half22float2(p2[o]); a2 += f2.x; b2 += f2.y;
        float2 f3 = __half22float2(p3[o]); a3 += f3.x; b3 += f3.y;
        float2 f4 = __half22float2(p4[o]); a4 += f4.x; b4 += f4.y;
    }

    float acc = 0.f;
#pragma unroll 2
    for (int x = x0; x < x0 + XC; ++x) {
        const int xp = x + PAD;
        if (xp < NX) {
            const size_t o = (size_t)xp * HALF_PLANE;
            float2 f0 = __half22float2(p0[o]); a0 += f0.x; b0 += f0.y;
            float2 f1 = __half22float2(p1[o]); a1 += f1.x; b1 += f1.y;
            float2 f2 = __half22float2(p2[o]); a2 += f2.x; b2 += f2.y;
            float2 f3 = __half22float2(p3[o]); a3 += f3.x; b3 += f3.y;
            float2 f4 = __half22float2(p4[o]); a4 += f4.x; b4 += f4.y;
        }
        {
            const float cross = a4 - a0 * a1 * WS_INV;
            const float ivar  = a2 - a0 * a0 * WS_INV;
            const float jvar  = a3 - a1 * a1 * WS_INV;
            acc += (cross * cross) / (ivar * jvar + EPS);
        }
        {
            const float cross = b4 - b0 * b1 * WS_INV;
            const float ivar  = b2 - b0 * b0 * WS_INV;
            const float jvar  = b3 - b1 * b1 * WS_INV;
            acc += (cross * cross) / (ivar * jvar + EPS);
        }
        const int xm = x - PAD;
        if (xm >= 0) {
            const size_t o = (size_t)xm * HALF_PLANE;
            float2 f0 = __half22float2(p0[o]); a0 -= f0.x; b0 -= f0.y;
            float2 f1 = __half22float2(p1[o]); a1 -= f1.x; b1 -= f1.y;
            float2 f2 = __half22float2(p2[o]); a2 -= f2.x; b2 -= f2.y;
            float2 f3 = __half22float2(p3[o]); a3 -= f3.x; b3 -= f3.y;
            float2 f4 = __half22float2(p4[o]); a4 -= f4.x; b4 -= f4.y;
        }
    }

    __shared__ float red[256];
    red[threadIdx.x] = acc;
    __syncthreads();
#pragma unroll
    for (int o = 128; o > 0; o >>= 1) {
        if (threadIdx.x < o) red[threadIdx.x] += red[threadIdx.x + o];
        __syncthreads();
    }
    if (threadIdx.x == 0) atomicAdd(&g_accum, (double)red[0]);
}

extern "C" void kernel_launch(void* const* d_in, const int* in_sizes, int n_in,
                              void* d_out, int out_size) {
    const float* I = (const float*)d_in[0];
    const float* J = (const float*)d_in[1];
    float* out = (float*)d_out;

    zero_accum_kernel<<<1, 1>>>();
    pass12<<<NB * NX, dim3(NZ2, 2)>>>(I, J);
    {
        dim3 grid((NB * HALF_PLANE) / 256, XCHUNKS);
        pass3_x_ncc<<<grid, 256>>>();
    }
    finalize_kernel<<<1, 1>>>(out);
}

// round 8
// speedup vs baseline: 3.7378x; 1.1988x over previous
#include <cuda_runtime.h>
#include <cuda_fp16.h>

#define NX 192
#define NY 192
#define NZ 192
#define NB 2
#define WIN 9
#define PAD 4
#define WS_INV (1.0f / 729.0f)
#define EPS 1e-5f

#define YC 48                   /* y-chunk per (blockIdx half, threadIdx.y) */
#define XCHUNKS 8
#define XC (NX / XCHUNKS)       /* 24 */
#define NZ2 (NZ / 2)            /* 96 float2/half2 per row */

constexpr size_t NTOT  = (size_t)NB * NX * NY * NZ;   // 14,155,776
constexpr size_t NTOT4 = NTOT / 4;                    // uint2 (4 halfs) per channel
constexpr int QUAD_PLANE = NY * NZ / 4;               // uint2 per x-slice = 9216

// Scratch: 5 channels {I_sum, J_sum, I2_sum, J2_sum, IJ_sum}, Z+Y filtered, fp16.
__device__ __half  g_buf[5 * NTOT];
__device__ double  g_accum;

// Persistent-state management: dedicated kernels (proven; fused variants failed).
__global__ void zero_accum_kernel() { g_accum = 0.0; }
__global__ void finalize_kernel(float* __restrict__ out) {
    out[0] = (float)(-g_accum / (double)NTOT);
}

// ---------------------------------------------------------------------------
// pass12: fused Z-filter + Y-filter. Thread = float2 z-pair; threadIdx.y = y
// sub-chunk; blockIdx selects (b,x) and y-half -> grid 768 for occupancy.
// Shared-middle tap decomposition, half2 ring, software-pipelined row loads.
// ---------------------------------------------------------------------------
__global__ __launch_bounds__(192) void pass12(const float* __restrict__ I,
                                              const float* __restrict__ J) {
    __shared__ float2  sIf[2][NZ2 + PAD];          // 100 float2 per chunk
    __shared__ float2  sJf[2][NZ2 + PAD];
    __shared__ __half2 ring[2][9][5][NZ2];         // 34.56 KB

    const int c    = threadIdx.y;                  // sub-chunk 0/1
    const int tz   = threadIdx.x;                  // 0..95
    const int id   = blockIdx.x;                   // 0 .. NB*NX*2-1
    const int half = id & 1;
    const int bx   = id >> 1;                      // (b,x): 0..NB*NX-1
    const size_t planeBase = (size_t)bx * NY * NZ;
    const int y0 = (half * 2 + c) * YC;
    const int ylEnd = y0 + YC + PAD;

    if (tz < 2) {   // z halo: 2 float2 each side
        sIf[c][tz] = make_float2(0.f, 0.f);
        sJf[c][tz] = make_float2(0.f, 0.f);
        sIf[c][NZ2 + 2 + tz] = make_float2(0.f, 0.f);
        sJf[c][NZ2 + 2 + tz] = make_float2(0.f, 0.f);
    }

    const float2* __restrict__ I2 = reinterpret_cast<const float2*>(I + planeBase);
    const float2* __restrict__ J2 = reinterpret_cast<const float2*>(J + planeBase);
    __half2* __restrict__ h2buf = reinterpret_cast<__half2*>(g_buf);

    const int yl0 = y0 - PAD;
    float2 aI = make_float2(0.f, 0.f), aJ = make_float2(0.f, 0.f);
    if (yl0 >= 0) {
        aI = I2[(size_t)yl0 * NZ2 + tz];
        aJ = J2[(size_t)yl0 * NZ2 + tz];
    }

    float sA0 = 0.f, sA1 = 0.f, sA2 = 0.f, sA3 = 0.f, sA4 = 0.f;
    float sB0 = 0.f, sB1 = 0.f, sB2 = 0.f, sB3 = 0.f, sB4 = 0.f;
    int slot = ((yl0 % 9) + 9) % 9;

    for (int yl = yl0; yl < ylEnd; ++yl) {
        __syncthreads();                   // prior row's taps consumed
        sIf[c][tz + 2] = aI;
        sJf[c][tz + 2] = aJ;
        __syncthreads();

        // Prefetch next row (overlaps tap compute).
        const int yn = yl + 1;
        if (yn >= 0 && yn < NY && yn < ylEnd) {
            aI = I2[(size_t)yn * NZ2 + tz];
            aJ = J2[(size_t)yn * NZ2 + tz];
        } else {
            aI = make_float2(0.f, 0.f);
            aJ = make_float2(0.f, 0.f);
        }

        // Window u[0..9] = raw z (2*tz-4 .. 2*tz+5), aligned float2 reads.
        float u[10], v[10];
#pragma unroll
        for (int j = 0; j < 5; ++j) {
            const float2 tu = sIf[c][tz + j];
            const float2 tv = sJf[c][tz + j];
            u[2 * j] = tu.x; u[2 * j + 1] = tu.y;
            v[2 * j] = tv.x; v[2 * j + 1] = tv.y;
        }
        // Shared middle (taps 1..8), then edge taps for the two outputs.
        float m0 = 0.f, m1 = 0.f, m2 = 0.f, m3 = 0.f, m4 = 0.f;
#pragma unroll
        for (int i = 1; i < 9; ++i) {
            m0 += u[i];             m1 += v[i];
            m2 = fmaf(u[i], u[i], m2);
            m3 = fmaf(v[i], v[i], m3);
            m4 = fmaf(u[i], v[i], m4);
        }
        const float qA0 = m0 + u[0],                 qB0 = m0 + u[9];
        const float qA1 = m1 + v[0],                 qB1 = m1 + v[9];
        const float qA2 = fmaf(u[0], u[0], m2),      qB2 = fmaf(u[9], u[9], m2);
        const float qA3 = fmaf(v[0], v[0], m3),      qB3 = fmaf(v[9], v[9], m3);
        const float qA4 = fmaf(u[0], v[0], m4),      qB4 = fmaf(u[9], v[9], m4);

        sA0 += qA0; sA1 += qA1; sA2 += qA2; sA3 += qA3; sA4 += qA4;
        sB0 += qB0; sB1 += qB1; sB2 += qB2; sB3 += qB3; sB4 += qB4;

        ring[c][slot][0][tz] = __floats2half2_rn(qA0, qB0);
        ring[c][slot][1][tz] = __floats2half2_rn(qA1, qB1);
        ring[c][slot][2][tz] = __floats2half2_rn(qA2, qB2);
        ring[c][slot][3][tz] = __floats2half2_rn(qA3, qB3);
        ring[c][slot][4][tz] = __floats2half2_rn(qA4, qB4);

        if (yl >= y0 + PAD) {
            const int yo = yl - PAD;
            const size_t o = planeBase / 2 + (size_t)yo * NZ2 + tz;
            h2buf[0 * (NTOT / 2) + o] = __floats2half2_rn(sA0, sB0);
            h2buf[1 * (NTOT / 2) + o] = __floats2half2_rn(sA1, sB1);
            h2buf[2 * (NTOT / 2) + o] = __floats2half2_rn(sA2, sB2);
            h2buf[3 * (NTOT / 2) + o] = __floats2half2_rn(sA3, sB3);
            h2buf[4 * (NTOT / 2) + o] = __floats2half2_rn(sA4, sB4);
            // Row yl-8 lives in slot (slot+1)%9 (read before next overwrite).
            const int so = (slot + 1 == 9) ? 0 : slot + 1;
            float2 f;
            f = __half22float2(ring[c][so][0][tz]); sA0 -= f.x; sB0 -= f.y;
            f = __half22float2(ring[c][so][1][tz]); sA1 -= f.x; sB1 -= f.y;
            f = __half22float2(ring[c][so][2][tz]); sA2 -= f.x; sB2 -= f.y;
            f = __half22float2(ring[c][so][3][tz]); sA3 -= f.x; sB3 -= f.y;
            f = __half22float2(ring[c][so][4][tz]); sA4 -= f.x; sB4 -= f.y;
        }
        slot = (slot + 1 == 9) ? 0 : slot + 1;
    }
}

// ---------------------------------------------------------------------------
// pass3: sliding 9-slice window along X, fused NCC + mean. Each thread owns
// 4 consecutive z-voxels (uint2 = 2 half2 per channel -> LDG.64, 2x MLP).
// X split into XCHUNKS=8 ranges. Proven conditional loop structure; macros
// replaced with lambdas (R7 died to macro identifier capture).
// ---------------------------------------------------------------------------
__global__ __launch_bounds__(256) void pass3_x_ncc() {
    const int x0 = blockIdx.y * XC;
    const int t  = blockIdx.x * blockDim.x + threadIdx.x;  // 0 .. NB*QUAD_PLANE-1
    const int b  = t / QUAD_PLANE;
    const int yz = t % QUAD_PLANE;

    const uint2* __restrict__ pk[5];
    {
        const uint2* base = reinterpret_cast<const uint2*>(g_buf) +
                            (size_t)b * NX * QUAD_PLANE + yz;
#pragma unroll
        for (int k = 0; k < 5; ++k) pk[k] = base + (size_t)k * NTOT4;
    }

    float s[5][4];
#pragma unroll
    for (int k = 0; k < 5; ++k)
#pragma unroll
        for (int l = 0; l < 4; ++l) s[k][l] = 0.f;

    auto slice_add = [&](int xs) {
        const size_t o = (size_t)xs * QUAD_PLANE;
#pragma unroll
        for (int k = 0; k < 5; ++k) {
            const uint2 w = pk[k][o];
            const float2 fl = __half22float2(*reinterpret_cast<const __half2*>(&w.x));
            const float2 fh = __half22float2(*reinterpret_cast<const __half2*>(&w.y));
            s[k][0] += fl.x; s[k][1] += fl.y; s[k][2] += fh.x; s[k][3] += fh.y;
        }
    };
    auto slice_sub = [&](int xs) {
        const size_t o = (size_t)xs * QUAD_PLANE;
#pragma unroll
        for (int k = 0; k < 5; ++k) {
            const uint2 w = pk[k][o];
            const float2 fl = __half22float2(*reinterpret_cast<const __half2*>(&w.x));
            const float2 fh = __half22float2(*reinterpret_cast<const __half2*>(&w.y));
            s[k][0] -= fl.x; s[k][1] -= fl.y; s[k][2] -= fh.x; s[k][3] -= fh.y;
        }
    };

    const int pre0 = (x0 - PAD > 0) ? (x0 - PAD) : 0;
#pragma unroll 4
    for (int x = pre0; x < x0 + PAD; ++x) slice_add(x);

    float acc = 0.f;
#pragma unroll 2
    for (int x = x0; x < x0 + XC; ++x) {
        const int xp = x + PAD;
        if (xp < NX) slice_add(xp);
#pragma unroll
        for (int l = 0; l < 4; ++l) {
            const float cross = s[4][l] - s[0][l] * s[1][l] * WS_INV;
            const float ivar  = s[2][l] - s[0][l] * s[0][l] * WS_INV;
            const float jvar  = s[3][l] - s[1][l] * s[1][l] * WS_INV;
            acc += (cross * cross) / (ivar * jvar + EPS);
        }
        const int xm = x - PAD;
        if (xm >= 0) slice_sub(xm);
    }

    __shared__ float red[256];
    red[threadIdx.x] = acc;
    __syncthreads();
#pragma unroll
    for (int o = 128; o > 0; o >>= 1) {
        if (threadIdx.x < o) red[threadIdx.x] += red[threadIdx.x + o];
        __syncthreads();
    }
    if (threadIdx.x == 0) atomicAdd(&g_accum, (double)red[0]);
}

extern "C" void kernel_launch(void* const* d_in, const int* in_sizes, int n_in,
                              void* d_out, int out_size) {
    const float* I = (const float*)d_in[0];
    const float* J = (const float*)d_in[1];
    float* out = (float*)d_out;

    zero_accum_kernel<<<1, 1>>>();
    pass12<<<NB * NX * 2, dim3(NZ2, 2)>>>(I, J);
    {
        dim3 grid((NB * QUAD_PLANE) / 256, XCHUNKS);
        pass3_x_ncc<<<grid, 256>>>();
    }
    finalize_kernel<<<1, 1>>>(out);
}